// round 8
// baseline (speedup 1.0000x reference)
#include <cuda_runtime.h>

// ---------------------------------------------------------------------------
// GraphSAGE 2-layer, N=100000 nodes, E edges, d: 128 -> 128 -> 64, fp32.
//   h   = relu( mean_agg(x) @ W1_l + b1 + x @ W1_r )
//   out = mean_agg(h @ W2_l) + b2 + h @ W2_r     (mean/matmul commuted)
// CSR gather aggregation + tensor-core GEMMs via 3xTF32 split
// (mma.sync.m16n8k8 tf32, hi/lo decomposition for ~fp32 accuracy).
// All persistent device state fully rewritten each call (replay idempotent).
// ---------------------------------------------------------------------------

#define NN 100000
#define EMAX 3200000
#define NB_SCAN 98            // ceil(NN/1024)

// float scratch
constexpr size_t AGG1  = 0;                              // mean_agg(x)   (N x 128)
constexpr size_t HBUF  = AGG1 + (size_t)NN * 128;        // h             (N x 128)
constexpr size_t TR2   = HBUF + (size_t)NN * 128;        // [t2|r2]       (N x 128)
constexpr size_t FTOT  = TR2 + (size_t)NN * 128;
__device__ float g_f[FTOT];

// int scratch  (CNT and TMP contiguous: one zeroing pass covers both)
constexpr size_t ROWPTR = 0;                             // NN+1
constexpr size_t CNT    = 100004;                        // NN
constexpr size_t TMP    = CNT + NN;                      // NN (contiguous)
constexpr size_t BSUM   = 300012;                        // 128
constexpr size_t SORTED = 300160;                        // EMAX
__device__ int g_i[SORTED + EMAX];
__device__ int g_idx64;

// ---- tf32 helpers ---------------------------------------------------------
__device__ __forceinline__ unsigned f2tf(float x) {
    unsigned r; asm("cvt.rna.tf32.f32 %0, %1;" : "=r"(r) : "f"(x)); return r;
}
__device__ __forceinline__ void split_tf32(float x, unsigned& hi, unsigned& lo) {
    hi = f2tf(x);
    lo = f2tf(x - __uint_as_float(hi));
}
__device__ __forceinline__ void mma8(float* d, const unsigned* a, const unsigned* b) {
    asm volatile(
        "mma.sync.aligned.m16n8k8.row.col.f32.tf32.tf32.f32 "
        "{%0,%1,%2,%3}, {%4,%5,%6,%7}, {%8,%9}, {%0,%1,%2,%3};"
        : "+f"(d[0]), "+f"(d[1]), "+f"(d[2]), "+f"(d[3])
        : "r"(a[0]), "r"(a[1]), "r"(a[2]), "r"(a[3]), "r"(b[0]), "r"(b[1]));
}

// ---------------------------------------------------------------------------
// int64 vs int32 edge_index detection (values < 2^17 => odd words all zero)
// ---------------------------------------------------------------------------
__global__ void detect_kernel(const void* ei) {
    const int* w = (const int*)ei;
    int lane = threadIdx.x;
    int nz = 0;
    for (int i = lane * 2 + 1; i < 512; i += 64) nz |= (w[i] != 0);
    unsigned m = __ballot_sync(0xffffffffu, nz);
    if (lane == 0) g_idx64 = (m == 0) ? 1 : 0;
}

__global__ void zero_int_kernel() {
    int i = blockIdx.x * blockDim.x + threadIdx.x;
    if (i < 2 * NN) g_i[CNT + i] = 0;
}

__device__ __forceinline__ void load_edge(const void* ei, int e, int E, int& src, int& dst) {
    if (g_idx64) {
        const long long* p = (const long long*)ei;
        src = (int)p[e]; dst = (int)p[(size_t)E + e];
    } else {
        const int* p = (const int*)ei;
        src = p[e]; dst = p[(size_t)E + e];
    }
}

__global__ void hist_kernel(const void* __restrict__ ei, int E) {
    int e = blockIdx.x * blockDim.x + threadIdx.x;
    if (e >= E) return;
    int dst;
    if (g_idx64) dst = (int)((const long long*)ei)[(size_t)E + e];
    else         dst = ((const int*)ei)[(size_t)E + e];
    atomicAdd(&g_i[CNT + dst], 1);
}

__global__ void scan_a_kernel() {
    __shared__ int s[1024];
    int t = threadIdx.x;
    int i = blockIdx.x * 1024 + t;
    int v = (i < NN) ? g_i[CNT + i] : 0;
    s[t] = v;
    __syncthreads();
#pragma unroll
    for (int off = 1; off < 1024; off <<= 1) {
        int u = (t >= off) ? s[t - off] : 0;
        __syncthreads();
        s[t] += u;
        __syncthreads();
    }
    if (i < NN) g_i[ROWPTR + i + 1] = s[t];
    if (t == 1023) g_i[BSUM + blockIdx.x] = s[1023];
}

__global__ void scan_b_kernel() {
    __shared__ int s[128];
    int t = threadIdx.x;
    int v = (t < NB_SCAN) ? g_i[BSUM + t] : 0;
    s[t] = v;
    __syncthreads();
#pragma unroll
    for (int off = 1; off < 128; off <<= 1) {
        int u = (t >= off) ? s[t - off] : 0;
        __syncthreads();
        s[t] += u;
        __syncthreads();
    }
    if (t < NB_SCAN) g_i[BSUM + t] = s[t] - v;   // exclusive
}

__global__ void scan_c_kernel() {
    int i = blockIdx.x * blockDim.x + threadIdx.x;
    if (i < NN) g_i[ROWPTR + i + 1] += g_i[BSUM + (i >> 10)];
    if (i == 0) g_i[ROWPTR] = 0;
}

__global__ void scatter_kernel(const void* __restrict__ ei, int E) {
    int e = blockIdx.x * blockDim.x + threadIdx.x;
    if (e >= E) return;
    int src, dst;
    load_edge(ei, e, E, src, dst);
    int pos = g_i[ROWPTR + dst] + atomicAdd(&g_i[TMP + dst], 1);
    g_i[SORTED + pos] = src;
}

// ---------------------------------------------------------------------------
// Layer-1 aggregation: one warp per dst node, register accumulation,
// writes the MEAN row (scale folded in). Unroll-4 for MLP.
// ---------------------------------------------------------------------------
__global__ __launch_bounds__(256) void agg1_kernel(const float* __restrict__ x) {
    int node = (int)(((size_t)blockIdx.x * blockDim.x + threadIdx.x) >> 5);
    if (node >= NN) return;
    int lane = threadIdx.x & 31;
    int beg = g_i[ROWPTR + node];
    int end = g_i[ROWPTR + node + 1];
    const int* srt = g_i + SORTED;
    float4 acc = make_float4(0.f, 0.f, 0.f, 0.f);
    int e = beg;
    for (; e + 4 <= end; e += 4) {
        int s0 = srt[e], s1 = srt[e + 1], s2 = srt[e + 2], s3 = srt[e + 3];
        float4 v0 = ((const float4*)(x + (size_t)s0 * 128))[lane];
        float4 v1 = ((const float4*)(x + (size_t)s1 * 128))[lane];
        float4 v2 = ((const float4*)(x + (size_t)s2 * 128))[lane];
        float4 v3 = ((const float4*)(x + (size_t)s3 * 128))[lane];
        acc.x += (v0.x + v1.x) + (v2.x + v3.x);
        acc.y += (v0.y + v1.y) + (v2.y + v3.y);
        acc.z += (v0.z + v1.z) + (v2.z + v3.z);
        acc.w += (v0.w + v1.w) + (v2.w + v3.w);
    }
    for (; e < end; e++) {
        float4 v = ((const float4*)(x + (size_t)srt[e] * 128))[lane];
        acc.x += v.x; acc.y += v.y; acc.z += v.z; acc.w += v.w;
    }
    float sc = 1.0f / fmaxf((float)(end - beg), 1.0f);
    ((float4*)(g_f + AGG1 + (size_t)node * 128))[lane] =
        make_float4(acc.x * sc, acc.y * sc, acc.z * sc, acc.w * sc);
}

// ---------------------------------------------------------------------------
// GEMM 1 (tensor core, 3xTF32): h = relu( agg1 @ W1_l + x @ W1_r + b1 )
//   128x128 block tile, 8 warps (4 row-groups x 2 col-groups, 32x64/warp),
//   K-tile 16 (two k8 steps). Smem strides conflict-free vs m16n8k8 frags.
// ---------------------------------------------------------------------------
__global__ __launch_bounds__(256) void gemm1_kernel(
    const float* __restrict__ x, const float* __restrict__ W1l,
    const float* __restrict__ b1, const float* __restrict__ W1r) {
    __shared__ unsigned Ah[128][20], Al[128][20];
    __shared__ unsigned Bh[16][136], Bl[16][136];
    int t = threadIdx.x, lane = t & 31, wid = t >> 5;
    int row0 = blockIdx.x * 128;
    int warp_m = (wid & 3) * 32;
    int warp_n = (wid >> 2) * 64;
    int g = lane >> 2, tg = lane & 3;

    float acc[2][8][4];
#pragma unroll
    for (int mt = 0; mt < 2; mt++)
#pragma unroll
        for (int nt = 0; nt < 8; nt++)
#pragma unroll
            for (int c = 0; c < 4; c++) acc[mt][nt][c] = 0.f;

    const float* agg1 = g_f + AGG1;

    for (int pair = 0; pair < 2; pair++) {
        const float* A = pair ? x : agg1;
        const float* B = pair ? W1r : W1l;
        for (int kt = 0; kt < 128; kt += 16) {
#pragma unroll
            for (int l = 0; l < 2; l++) {                       // A tile 128x16
                int q = t + l * 256;
                int m = q >> 2, k4 = (q & 3) * 4;
                int grow = row0 + m;
                float4 v = make_float4(0.f, 0.f, 0.f, 0.f);
                if (grow < NN) v = *(const float4*)(A + (size_t)grow * 128 + kt + k4);
                unsigned h0, l0;
                split_tf32(v.x, h0, l0); Ah[m][k4 + 0] = h0; Al[m][k4 + 0] = l0;
                split_tf32(v.y, h0, l0); Ah[m][k4 + 1] = h0; Al[m][k4 + 1] = l0;
                split_tf32(v.z, h0, l0); Ah[m][k4 + 2] = h0; Al[m][k4 + 2] = l0;
                split_tf32(v.w, h0, l0); Ah[m][k4 + 3] = h0; Al[m][k4 + 3] = l0;
            }
#pragma unroll
            for (int l = 0; l < 2; l++) {                       // B tile 16x128
                int q = t + l * 256;
                int bk = q >> 5, bn = (q & 31) * 4;
                float4 v = *(const float4*)(B + (size_t)(kt + bk) * 128 + bn);
                unsigned h0, l0;
                split_tf32(v.x, h0, l0); Bh[bk][bn + 0] = h0; Bl[bk][bn + 0] = l0;
                split_tf32(v.y, h0, l0); Bh[bk][bn + 1] = h0; Bl[bk][bn + 1] = l0;
                split_tf32(v.z, h0, l0); Bh[bk][bn + 2] = h0; Bl[bk][bn + 2] = l0;
                split_tf32(v.w, h0, l0); Bh[bk][bn + 3] = h0; Bl[bk][bn + 3] = l0;
            }
            __syncthreads();
#pragma unroll
            for (int ks = 0; ks < 2; ks++) {
                int k0 = ks * 8;
                unsigned ah[2][4], al[2][4];
#pragma unroll
                for (int mt = 0; mt < 2; mt++) {
                    int r0 = warp_m + mt * 16;
                    ah[mt][0] = Ah[r0 + g][k0 + tg];       al[mt][0] = Al[r0 + g][k0 + tg];
                    ah[mt][1] = Ah[r0 + g + 8][k0 + tg];   al[mt][1] = Al[r0 + g + 8][k0 + tg];
                    ah[mt][2] = Ah[r0 + g][k0 + tg + 4];   al[mt][2] = Al[r0 + g][k0 + tg + 4];
                    ah[mt][3] = Ah[r0 + g + 8][k0 + tg + 4]; al[mt][3] = Al[r0 + g + 8][k0 + tg + 4];
                }
#pragma unroll
                for (int nt = 0; nt < 8; nt++) {
                    int n0 = warp_n + nt * 8;
                    unsigned bh[2], bl[2];
                    bh[0] = Bh[k0 + tg][n0 + g]; bh[1] = Bh[k0 + tg + 4][n0 + g];
                    bl[0] = Bl[k0 + tg][n0 + g]; bl[1] = Bl[k0 + tg + 4][n0 + g];
#pragma unroll
                    for (int mt = 0; mt < 2; mt++) {
                        mma8(acc[mt][nt], al[mt], bh);
                        mma8(acc[mt][nt], ah[mt], bl);
                        mma8(acc[mt][nt], ah[mt], bh);
                    }
                }
            }
            __syncthreads();
        }
    }

    float* h = g_f + HBUF;
#pragma unroll
    for (int mt = 0; mt < 2; mt++) {
#pragma unroll
        for (int nt = 0; nt < 8; nt++) {
            int col = warp_n + nt * 8 + tg * 2;
            float bx = b1[col], by = b1[col + 1];
            int rlo = row0 + warp_m + mt * 16 + g;
            if (rlo < NN) {
                float2 o;
                o.x = fmaxf(acc[mt][nt][0] + bx, 0.f);
                o.y = fmaxf(acc[mt][nt][1] + by, 0.f);
                *(float2*)(h + (size_t)rlo * 128 + col) = o;
            }
            int rhi = rlo + 8;
            if (rhi < NN) {
                float2 o;
                o.x = fmaxf(acc[mt][nt][2] + bx, 0.f);
                o.y = fmaxf(acc[mt][nt][3] + by, 0.f);
                *(float2*)(h + (size_t)rhi * 128 + col) = o;
            }
        }
    }
}

// ---------------------------------------------------------------------------
// GEMM 2 (tensor core, 3xTF32): TR2 = h @ [W2_l | W2_r]  (M=NN, N=128, K=128)
// ---------------------------------------------------------------------------
__global__ __launch_bounds__(256) void gemm2_kernel(
    const float* __restrict__ W2l, const float* __restrict__ W2r) {
    __shared__ unsigned Ah[128][20], Al[128][20];
    __shared__ unsigned Bh[16][136], Bl[16][136];
    int t = threadIdx.x, lane = t & 31, wid = t >> 5;
    int row0 = blockIdx.x * 128;
    int warp_m = (wid & 3) * 32;
    int warp_n = (wid >> 2) * 64;
    int g = lane >> 2, tg = lane & 3;

    float acc[2][8][4];
#pragma unroll
    for (int mt = 0; mt < 2; mt++)
#pragma unroll
        for (int nt = 0; nt < 8; nt++)
#pragma unroll
            for (int c = 0; c < 4; c++) acc[mt][nt][c] = 0.f;

    const float* hsrc = g_f + HBUF;

    for (int kt = 0; kt < 128; kt += 16) {
#pragma unroll
        for (int l = 0; l < 2; l++) {                       // A tile 128x16
            int q = t + l * 256;
            int m = q >> 2, k4 = (q & 3) * 4;
            int grow = row0 + m;
            float4 v = make_float4(0.f, 0.f, 0.f, 0.f);
            if (grow < NN) v = *(const float4*)(hsrc + (size_t)grow * 128 + kt + k4);
            unsigned h0, l0;
            split_tf32(v.x, h0, l0); Ah[m][k4 + 0] = h0; Al[m][k4 + 0] = l0;
            split_tf32(v.y, h0, l0); Ah[m][k4 + 1] = h0; Al[m][k4 + 1] = l0;
            split_tf32(v.z, h0, l0); Ah[m][k4 + 2] = h0; Al[m][k4 + 2] = l0;
            split_tf32(v.w, h0, l0); Ah[m][k4 + 3] = h0; Al[m][k4 + 3] = l0;
        }
#pragma unroll
        for (int l = 0; l < 2; l++) {                       // B tile 16x128 = [W2l|W2r]
            int q = t + l * 256;
            int bk = q >> 5, bn = (q & 31) * 4;
            float4 v;
            if (bn < 64) v = *(const float4*)(W2l + (size_t)(kt + bk) * 64 + bn);
            else         v = *(const float4*)(W2r + (size_t)(kt + bk) * 64 + (bn - 64));
            unsigned h0, l0;
            split_tf32(v.x, h0, l0); Bh[bk][bn + 0] = h0; Bl[bk][bn + 0] = l0;
            split_tf32(v.y, h0, l0); Bh[bk][bn + 1] = h0; Bl[bk][bn + 1] = l0;
            split_tf32(v.z, h0, l0); Bh[bk][bn + 2] = h0; Bl[bk][bn + 2] = l0;
            split_tf32(v.w, h0, l0); Bh[bk][bn + 3] = h0; Bl[bk][bn + 3] = l0;
        }
        __syncthreads();
#pragma unroll
        for (int ks = 0; ks < 2; ks++) {
            int k0 = ks * 8;
            unsigned ah[2][4], al[2][4];
#pragma unroll
            for (int mt = 0; mt < 2; mt++) {
                int r0 = warp_m + mt * 16;
                ah[mt][0] = Ah[r0 + g][k0 + tg];       al[mt][0] = Al[r0 + g][k0 + tg];
                ah[mt][1] = Ah[r0 + g + 8][k0 + tg];   al[mt][1] = Al[r0 + g + 8][k0 + tg];
                ah[mt][2] = Ah[r0 + g][k0 + tg + 4];   al[mt][2] = Al[r0 + g][k0 + tg + 4];
                ah[mt][3] = Ah[r0 + g + 8][k0 + tg + 4]; al[mt][3] = Al[r0 + g + 8][k0 + tg + 4];
            }
#pragma unroll
            for (int nt = 0; nt < 8; nt++) {
                int n0 = warp_n + nt * 8;
                unsigned bh[2], bl[2];
                bh[0] = Bh[k0 + tg][n0 + g]; bh[1] = Bh[k0 + tg + 4][n0 + g];
                bl[0] = Bl[k0 + tg][n0 + g]; bl[1] = Bl[k0 + tg + 4][n0 + g];
#pragma unroll
                for (int mt = 0; mt < 2; mt++) {
                    mma8(acc[mt][nt], al[mt], bh);
                    mma8(acc[mt][nt], ah[mt], bl);
                    mma8(acc[mt][nt], ah[mt], bh);
                }
            }
        }
        __syncthreads();
    }

    float* tr2 = g_f + TR2;
#pragma unroll
    for (int mt = 0; mt < 2; mt++) {
#pragma unroll
        for (int nt = 0; nt < 8; nt++) {
            int col = warp_n + nt * 8 + tg * 2;
            int rlo = row0 + warp_m + mt * 16 + g;
            if (rlo < NN) {
                *(float2*)(tr2 + (size_t)rlo * 128 + col) =
                    make_float2(acc[mt][nt][0], acc[mt][nt][1]);
            }
            int rhi = rlo + 8;
            if (rhi < NN) {
                *(float2*)(tr2 + (size_t)rhi * 128 + col) =
                    make_float2(acc[mt][nt][2], acc[mt][nt][3]);
            }
        }
    }
}

// ---------------------------------------------------------------------------
// Layer-2 aggregation fused with epilogue:
//   out[i] = mean_{j in N(i)} t2[j] + b2 + r2[i]
// ---------------------------------------------------------------------------
__global__ __launch_bounds__(256) void agg2_kernel(const float* __restrict__ b2,
                                                   float* __restrict__ out) {
    int node = (int)(((size_t)blockIdx.x * blockDim.x + threadIdx.x) >> 5);
    if (node >= NN) return;
    int lane = threadIdx.x & 31;
    int beg = g_i[ROWPTR + node];
    int end = g_i[ROWPTR + node + 1];
    const int* srt = g_i + SORTED;
    const float* t2 = g_f + TR2;
    float2 acc = make_float2(0.f, 0.f);
    int e = beg;
    for (; e + 4 <= end; e += 4) {
        int s0 = srt[e], s1 = srt[e + 1], s2 = srt[e + 2], s3 = srt[e + 3];
        float2 v0 = ((const float2*)(t2 + (size_t)s0 * 128))[lane];
        float2 v1 = ((const float2*)(t2 + (size_t)s1 * 128))[lane];
        float2 v2 = ((const float2*)(t2 + (size_t)s2 * 128))[lane];
        float2 v3 = ((const float2*)(t2 + (size_t)s3 * 128))[lane];
        acc.x += (v0.x + v1.x) + (v2.x + v3.x);
        acc.y += (v0.y + v1.y) + (v2.y + v3.y);
    }
    for (; e < end; e++) {
        float2 v = ((const float2*)(t2 + (size_t)srt[e] * 128))[lane];
        acc.x += v.x; acc.y += v.y;
    }
    float sc = 1.0f / fmaxf((float)(end - beg), 1.0f);
    float2 r = ((const float2*)(t2 + (size_t)node * 128 + 64))[lane];
    float2 bb = ((const float2*)b2)[lane];
    float2 o;
    o.x = acc.x * sc + bb.x + r.x;
    o.y = acc.y * sc + bb.y + r.y;
    ((float2*)(out + (size_t)node * 64))[lane] = o;
}

extern "C" void kernel_launch(void* const* d_in, const int* in_sizes, int n_in,
                              void* d_out, int out_size) {
    const float* x   = (const float*)d_in[0];
    const float* W1l = (const float*)d_in[1];
    const float* b1  = (const float*)d_in[2];
    const float* W1r = (const float*)d_in[3];
    const float* W2l = (const float*)d_in[4];
    const float* b2  = (const float*)d_in[5];
    const float* W2r = (const float*)d_in[6];
    const void*  ei  = d_in[7];
    int E = in_sizes[7] / 2;
    if (E > EMAX) E = EMAX;
    float* out = (float*)d_out;

    detect_kernel<<<1, 32>>>(ei);
    zero_int_kernel<<<(2 * NN + 255) / 256, 256>>>();
    hist_kernel<<<(E + 255) / 256, 256>>>(ei, E);
    scan_a_kernel<<<NB_SCAN, 1024>>>();
    scan_b_kernel<<<1, 128>>>();
    scan_c_kernel<<<(NN + 255) / 256, 256>>>();
    scatter_kernel<<<(E + 255) / 256, 256>>>(ei, E);

    agg1_kernel<<<(NN * 32 + 255) / 256, 256>>>(x);
    gemm1_kernel<<<(NN + 127) / 128, 256>>>(x, W1l, b1, W1r);
    gemm2_kernel<<<(NN + 127) / 128, 256>>>(W2l, W2r);
    agg2_kernel<<<(NN * 32 + 255) / 256, 256>>>(b2, out);
}

// round 11
// speedup vs baseline: 1.4718x; 1.4718x over previous
#include <cuda_runtime.h>
#include <cuda_bf16.h>
#include <cstdint>

// ---------------------------------------------------------------------------
// GraphSAGE 2-layer, N=100000 nodes, E edges, d: 128 -> 128 -> 64, fp32.
//   h   = relu( mean_agg(x) @ W1_l + b1 + x @ W1_r )
//   out = mean_agg(h @ W2_l) + b2 + h @ W2_r     (mean/matmul commuted)
// CSR gather aggregation + legacy mma.sync.m16n8k16 bf16 GEMMs with 2-term
// bf16 split (h+l, 3 products, fp32 accumulate). tcgen05 is unavailable:
// the harness builds compute_103 PTX (no 'a'), which gates it off.
// All persistent device state fully rewritten each call (replay idempotent).
// ---------------------------------------------------------------------------

#define NN 100000
#define EMAX 3200000
#define NB_SCAN 98            // ceil(NN/1024)

// float scratch
constexpr size_t AGG1  = 0;                              // mean_agg(x)   (N x 128)
constexpr size_t HBUF  = AGG1 + (size_t)NN * 128;        // h             (N x 128)
constexpr size_t TR2   = HBUF + (size_t)NN * 128;        // [t2|r2]       (N x 128)
constexpr size_t FTOT  = TR2 + (size_t)NN * 128;
__device__ float g_f[FTOT];

// int scratch  (CNT and TMP contiguous: one zeroing pass covers both)
constexpr size_t ROWPTR = 0;                             // NN+1
constexpr size_t CNT    = 100004;                        // NN
constexpr size_t TMP    = CNT + NN;                      // NN (contiguous)
constexpr size_t BSUM   = 300012;                        // 128
constexpr size_t SORTED = 300160;                        // EMAX
__device__ int g_i[SORTED + EMAX];
__device__ int g_idx64;

// ---- bf16 split + legacy mma helpers --------------------------------------
__device__ __forceinline__ void bsplit(float x, unsigned short& h, unsigned short& l) {
    __nv_bfloat16 hb = __float2bfloat16(x);
    __nv_bfloat16 lb = __float2bfloat16(x - __bfloat162float(hb));
    h = __bfloat16_as_ushort(hb);
    l = __bfloat16_as_ushort(lb);
}
__device__ __forceinline__ void mma16(float* d, const unsigned* a, const unsigned* b) {
    asm volatile(
        "mma.sync.aligned.m16n8k16.row.col.f32.bf16.bf16.f32 "
        "{%0,%1,%2,%3}, {%4,%5,%6,%7}, {%8,%9}, {%0,%1,%2,%3};"
        : "+f"(d[0]), "+f"(d[1]), "+f"(d[2]), "+f"(d[3])
        : "r"(a[0]), "r"(a[1]), "r"(a[2]), "r"(a[3]), "r"(b[0]), "r"(b[1]));
}

// ---------------------------------------------------------------------------
// int64 vs int32 edge_index detection (values < 2^17 => odd words all zero)
// ---------------------------------------------------------------------------
__global__ void detect_kernel(const void* ei) {
    const int* w = (const int*)ei;
    int lane = threadIdx.x;
    int nz = 0;
    for (int i = lane * 2 + 1; i < 512; i += 64) nz |= (w[i] != 0);
    unsigned m = __ballot_sync(0xffffffffu, nz);
    if (lane == 0) g_idx64 = (m == 0) ? 1 : 0;
}

__global__ void zero_int_kernel() {
    int i = blockIdx.x * blockDim.x + threadIdx.x;
    if (i < 2 * NN) g_i[CNT + i] = 0;
}

__device__ __forceinline__ void load_edge(const void* ei, int e, int E, int& src, int& dst) {
    if (g_idx64) {
        const long long* p = (const long long*)ei;
        src = (int)p[e]; dst = (int)p[(size_t)E + e];
    } else {
        const int* p = (const int*)ei;
        src = p[e]; dst = p[(size_t)E + e];
    }
}

__global__ void hist_kernel(const void* __restrict__ ei, int E) {
    int e = blockIdx.x * blockDim.x + threadIdx.x;
    if (e >= E) return;
    int dst;
    if (g_idx64) dst = (int)((const long long*)ei)[(size_t)E + e];
    else         dst = ((const int*)ei)[(size_t)E + e];
    atomicAdd(&g_i[CNT + dst], 1);
}

__global__ void scan_a_kernel() {
    __shared__ int s[1024];
    int t = threadIdx.x;
    int i = blockIdx.x * 1024 + t;
    int v = (i < NN) ? g_i[CNT + i] : 0;
    s[t] = v;
    __syncthreads();
#pragma unroll
    for (int off = 1; off < 1024; off <<= 1) {
        int u = (t >= off) ? s[t - off] : 0;
        __syncthreads();
        s[t] += u;
        __syncthreads();
    }
    if (i < NN) g_i[ROWPTR + i + 1] = s[t];
    if (t == 1023) g_i[BSUM + blockIdx.x] = s[1023];
}

__global__ void scan_b_kernel() {
    __shared__ int s[128];
    int t = threadIdx.x;
    int v = (t < NB_SCAN) ? g_i[BSUM + t] : 0;
    s[t] = v;
    __syncthreads();
#pragma unroll
    for (int off = 1; off < 128; off <<= 1) {
        int u = (t >= off) ? s[t - off] : 0;
        __syncthreads();
        s[t] += u;
        __syncthreads();
    }
    if (t < NB_SCAN) g_i[BSUM + t] = s[t] - v;   // exclusive
}

__global__ void scan_c_kernel() {
    int i = blockIdx.x * blockDim.x + threadIdx.x;
    if (i < NN) g_i[ROWPTR + i + 1] += g_i[BSUM + (i >> 10)];
    if (i == 0) g_i[ROWPTR] = 0;
}

__global__ void scatter_kernel(const void* __restrict__ ei, int E) {
    int e = blockIdx.x * blockDim.x + threadIdx.x;
    if (e >= E) return;
    int src, dst;
    load_edge(ei, e, E, src, dst);
    int pos = g_i[ROWPTR + dst] + atomicAdd(&g_i[TMP + dst], 1);
    g_i[SORTED + pos] = src;
}

// ---------------------------------------------------------------------------
// Layer-1 aggregation: one warp per dst node, register accumulation.
// ---------------------------------------------------------------------------
__global__ __launch_bounds__(256) void agg1_kernel(const float* __restrict__ x) {
    int node = (int)(((size_t)blockIdx.x * blockDim.x + threadIdx.x) >> 5);
    if (node >= NN) return;
    int lane = threadIdx.x & 31;
    int beg = g_i[ROWPTR + node];
    int end = g_i[ROWPTR + node + 1];
    const int* srt = g_i + SORTED;
    float4 acc = make_float4(0.f, 0.f, 0.f, 0.f);
    int e = beg;
    for (; e + 4 <= end; e += 4) {
        int s0 = srt[e], s1 = srt[e + 1], s2 = srt[e + 2], s3 = srt[e + 3];
        float4 v0 = ((const float4*)(x + (size_t)s0 * 128))[lane];
        float4 v1 = ((const float4*)(x + (size_t)s1 * 128))[lane];
        float4 v2 = ((const float4*)(x + (size_t)s2 * 128))[lane];
        float4 v3 = ((const float4*)(x + (size_t)s3 * 128))[lane];
        acc.x += (v0.x + v1.x) + (v2.x + v3.x);
        acc.y += (v0.y + v1.y) + (v2.y + v3.y);
        acc.z += (v0.z + v1.z) + (v2.z + v3.z);
        acc.w += (v0.w + v1.w) + (v2.w + v3.w);
    }
    for (; e < end; e++) {
        float4 v = ((const float4*)(x + (size_t)srt[e] * 128))[lane];
        acc.x += v.x; acc.y += v.y; acc.z += v.z; acc.w += v.w;
    }
    float sc = 1.0f / fmaxf((float)(end - beg), 1.0f);
    ((float4*)(g_f + AGG1 + (size_t)node * 128))[lane] =
        make_float4(acc.x * sc, acc.y * sc, acc.z * sc, acc.w * sc);
}

// ---------------------------------------------------------------------------
// Shared GEMM tile machinery (legacy bf16 m16n8k16).
// A tile: 128 rows x 16 k -> Ah/Al as packed bf16 pairs, word stride 12.
// B tile: 16 k x 128 n -> Bh/Bl as [n][k] ushort, stride 24 (=12 words).
// Fragment loads hit all-distinct banks (g*12 + tg mod 32 bijective).
// ---------------------------------------------------------------------------
struct GemmSmem {
    unsigned Ah[128][12], Al[128][12];
    unsigned short Bh[128][24], Bl[128][24];
};

__device__ __forceinline__ void fill_a16(GemmSmem& s, const float* A,
                                         int row0, int kt, int t) {
#pragma unroll
    for (int l = 0; l < 2; l++) {
        int i = t + l * 256;                 // 512 float4s = 128 rows x 4
        int m = i >> 2, q = i & 3;           // cols 4q..4q+3 -> pairs 2q, 2q+1
        float4 v = make_float4(0.f, 0.f, 0.f, 0.f);
        int gr = row0 + m;
        if (gr < NN) v = *(const float4*)(A + (size_t)gr * 128 + kt + q * 4);
        unsigned short h0, l0, h1, l1, h2, l2, h3, l3;
        bsplit(v.x, h0, l0); bsplit(v.y, h1, l1);
        bsplit(v.z, h2, l2); bsplit(v.w, h3, l3);
        s.Ah[m][2 * q + 0] = (unsigned)h0 | ((unsigned)h1 << 16);
        s.Ah[m][2 * q + 1] = (unsigned)h2 | ((unsigned)h3 << 16);
        s.Al[m][2 * q + 0] = (unsigned)l0 | ((unsigned)l1 << 16);
        s.Al[m][2 * q + 1] = (unsigned)l2 | ((unsigned)l3 << 16);
    }
}

// One K-16 step of the per-warp 32x64 tile: 2 mt x 8 nt x 3 products.
__device__ __forceinline__ void mma_step(GemmSmem& s, float acc[2][8][4],
                                         int warp_m, int warp_n, int g, int tg) {
    unsigned ah[2][4], al[2][4];
#pragma unroll
    for (int mt = 0; mt < 2; mt++) {
        int r = warp_m + mt * 16;
        ah[mt][0] = s.Ah[r + g][tg];      al[mt][0] = s.Al[r + g][tg];
        ah[mt][1] = s.Ah[r + g + 8][tg];  al[mt][1] = s.Al[r + g + 8][tg];
        ah[mt][2] = s.Ah[r + g][tg + 4];  al[mt][2] = s.Al[r + g][tg + 4];
        ah[mt][3] = s.Ah[r + g + 8][tg + 4]; al[mt][3] = s.Al[r + g + 8][tg + 4];
    }
#pragma unroll
    for (int nt = 0; nt < 8; nt++) {
        int n = warp_n + nt * 8 + g;
        unsigned bh[2], bl[2];
        bh[0] = ((const unsigned*)&s.Bh[n][0])[tg];
        bh[1] = ((const unsigned*)&s.Bh[n][0])[tg + 4];
        bl[0] = ((const unsigned*)&s.Bl[n][0])[tg];
        bl[1] = ((const unsigned*)&s.Bl[n][0])[tg + 4];
#pragma unroll
        for (int mt = 0; mt < 2; mt++) {
            mma16(acc[mt][nt], al[mt], bh);
            mma16(acc[mt][nt], ah[mt], bl);
            mma16(acc[mt][nt], ah[mt], bh);
        }
    }
}

// ---------------------------------------------------------------------------
// GEMM 1: h = relu( agg1 @ W1_l + x @ W1_r + b1 )
// ---------------------------------------------------------------------------
__global__ __launch_bounds__(256) void gemm1_kernel(
    const float* __restrict__ x, const float* __restrict__ W1l,
    const float* __restrict__ b1, const float* __restrict__ W1r) {
    __shared__ GemmSmem s;
    int t = threadIdx.x, lane = t & 31, wid = t >> 5;
    int row0 = blockIdx.x * 128;
    int warp_m = (wid & 3) * 32, warp_n = (wid >> 2) * 64;
    int g = lane >> 2, tg = lane & 3;

    float acc[2][8][4];
#pragma unroll
    for (int mt = 0; mt < 2; mt++)
#pragma unroll
        for (int nt = 0; nt < 8; nt++)
#pragma unroll
            for (int c = 0; c < 4; c++) acc[mt][nt][c] = 0.f;

    const float* agg1 = g_f + AGG1;

    for (int pair = 0; pair < 2; pair++) {
        const float* A = pair ? x : agg1;
        const float* B = pair ? W1r : W1l;
        for (int kt = 0; kt < 128; kt += 16) {
            fill_a16(s, A, row0, kt, t);
#pragma unroll
            for (int l = 0; l < 8; l++) {       // B: 16k x 128n
                int i = t + l * 256;
                int k = i >> 7, n = i & 127;
                float w = B[(size_t)(kt + k) * 128 + n];
                unsigned short h0, l0;
                bsplit(w, h0, l0);
                s.Bh[n][k] = h0;
                s.Bl[n][k] = l0;
            }
            __syncthreads();
            mma_step(s, acc, warp_m, warp_n, g, tg);
            __syncthreads();
        }
    }

    float* h = g_f + HBUF;
#pragma unroll
    for (int mt = 0; mt < 2; mt++) {
#pragma unroll
        for (int nt = 0; nt < 8; nt++) {
            int col = warp_n + nt * 8 + tg * 2;
            float bx = b1[col], by = b1[col + 1];
            int rlo = row0 + warp_m + mt * 16 + g;
            if (rlo < NN) {
                float2 o;
                o.x = fmaxf(acc[mt][nt][0] + bx, 0.f);
                o.y = fmaxf(acc[mt][nt][1] + by, 0.f);
                *(float2*)(h + (size_t)rlo * 128 + col) = o;
            }
            int rhi = rlo + 8;
            if (rhi < NN) {
                float2 o;
                o.x = fmaxf(acc[mt][nt][2] + bx, 0.f);
                o.y = fmaxf(acc[mt][nt][3] + by, 0.f);
                *(float2*)(h + (size_t)rhi * 128 + col) = o;
            }
        }
    }
}

// ---------------------------------------------------------------------------
// GEMM 2: TR2 = h @ [W2_l | W2_r]   (M = NN, N = 128, K = 128)
// ---------------------------------------------------------------------------
__global__ __launch_bounds__(256) void gemm2_kernel(
    const float* __restrict__ W2l, const float* __restrict__ W2r) {
    __shared__ GemmSmem s;
    int t = threadIdx.x, lane = t & 31, wid = t >> 5;
    int row0 = blockIdx.x * 128;
    int warp_m = (wid & 3) * 32, warp_n = (wid >> 2) * 64;
    int g = lane >> 2, tg = lane & 3;

    float acc[2][8][4];
#pragma unroll
    for (int mt = 0; mt < 2; mt++)
#pragma unroll
        for (int nt = 0; nt < 8; nt++)
#pragma unroll
            for (int c = 0; c < 4; c++) acc[mt][nt][c] = 0.f;

    const float* hsrc = g_f + HBUF;

    for (int kt = 0; kt < 128; kt += 16) {
        fill_a16(s, hsrc, row0, kt, t);
#pragma unroll
        for (int l = 0; l < 8; l++) {       // B: 16k x 128n = [W2l|W2r]
            int i = t + l * 256;
            int k = i >> 7, n = i & 127;
            float w = (n < 64) ? W2l[(size_t)(kt + k) * 64 + n]
                               : W2r[(size_t)(kt + k) * 64 + (n - 64)];
            unsigned short h0, l0;
            bsplit(w, h0, l0);
            s.Bh[n][k] = h0;
            s.Bl[n][k] = l0;
        }
        __syncthreads();
        mma_step(s, acc, warp_m, warp_n, g, tg);
        __syncthreads();
    }

    float* tr2 = g_f + TR2;
#pragma unroll
    for (int mt = 0; mt < 2; mt++) {
#pragma unroll
        for (int nt = 0; nt < 8; nt++) {
            int col = warp_n + nt * 8 + tg * 2;
            int rlo = row0 + warp_m + mt * 16 + g;
            if (rlo < NN) {
                *(float2*)(tr2 + (size_t)rlo * 128 + col) =
                    make_float2(acc[mt][nt][0], acc[mt][nt][1]);
            }
            int rhi = rlo + 8;
            if (rhi < NN) {
                *(float2*)(tr2 + (size_t)rhi * 128 + col) =
                    make_float2(acc[mt][nt][2], acc[mt][nt][3]);
            }
        }
    }
}

// ---------------------------------------------------------------------------
// Layer-2 aggregation fused with epilogue:
//   out[i] = mean_{j in N(i)} t2[j] + b2 + r2[i]
// ---------------------------------------------------------------------------
__global__ __launch_bounds__(256) void agg2_kernel(const float* __restrict__ b2,
                                                   float* __restrict__ out) {
    int node = (int)(((size_t)blockIdx.x * blockDim.x + threadIdx.x) >> 5);
    if (node >= NN) return;
    int lane = threadIdx.x & 31;
    int beg = g_i[ROWPTR + node];
    int end = g_i[ROWPTR + node + 1];
    const int* srt = g_i + SORTED;
    const float* t2 = g_f + TR2;
    float2 acc = make_float2(0.f, 0.f);
    int e = beg;
    for (; e + 4 <= end; e += 4) {
        int s0 = srt[e], s1 = srt[e + 1], s2 = srt[e + 2], s3 = srt[e + 3];
        float2 v0 = ((const float2*)(t2 + (size_t)s0 * 128))[lane];
        float2 v1 = ((const float2*)(t2 + (size_t)s1 * 128))[lane];
        float2 v2 = ((const float2*)(t2 + (size_t)s2 * 128))[lane];
        float2 v3 = ((const float2*)(t2 + (size_t)s3 * 128))[lane];
        acc.x += (v0.x + v1.x) + (v2.x + v3.x);
        acc.y += (v0.y + v1.y) + (v2.y + v3.y);
    }
    for (; e < end; e++) {
        float2 v = ((const float2*)(t2 + (size_t)srt[e] * 128))[lane];
        acc.x += v.x; acc.y += v.y;
    }
    float sc = 1.0f / fmaxf((float)(end - beg), 1.0f);
    float2 r = ((const float2*)(t2 + (size_t)node * 128 + 64))[lane];
    float2 bb = ((const float2*)b2)[lane];
    float2 o;
    o.x = acc.x * sc + bb.x + r.x;
    o.y = acc.y * sc + bb.y + r.y;
    ((float2*)(out + (size_t)node * 64))[lane] = o;
}

extern "C" void kernel_launch(void* const* d_in, const int* in_sizes, int n_in,
                              void* d_out, int out_size) {
    const float* x   = (const float*)d_in[0];
    const float* W1l = (const float*)d_in[1];
    const float* b1  = (const float*)d_in[2];
    const float* W1r = (const float*)d_in[3];
    const float* W2l = (const float*)d_in[4];
    const float* b2  = (const float*)d_in[5];
    const float* W2r = (const float*)d_in[6];
    const void*  ei  = d_in[7];
    int E = in_sizes[7] / 2;
    if (E > EMAX) E = EMAX;
    float* out = (float*)d_out;

    detect_kernel<<<1, 32>>>(ei);
    zero_int_kernel<<<(2 * NN + 255) / 256, 256>>>();
    hist_kernel<<<(E + 255) / 256, 256>>>(ei, E);
    scan_a_kernel<<<NB_SCAN, 1024>>>();
    scan_b_kernel<<<1, 128>>>();
    scan_c_kernel<<<(NN + 255) / 256, 256>>>();
    scatter_kernel<<<(E + 255) / 256, 256>>>(ei, E);

    agg1_kernel<<<(NN * 32 + 255) / 256, 256>>>(x);
    gemm1_kernel<<<(NN + 127) / 128, 256>>>(x, W1l, b1, W1r);
    gemm2_kernel<<<(NN + 127) / 128, 256>>>(W2l, W2r);
    agg2_kernel<<<(NN * 32 + 255) / 256, 256>>>(b2, out);
}

// round 12
// speedup vs baseline: 1.4999x; 1.0191x over previous
#include <cuda_runtime.h>
#include <cuda_bf16.h>
#include <cstdint>

// ---------------------------------------------------------------------------
// GraphSAGE 2-layer, N=100000 nodes, E edges, d: 128 -> 128 -> 64, fp32.
//   h   = relu( mean_agg(x) @ W1_l + b1 + x @ W1_r )
//   out = mean_agg(h @ W2_l) + b2 + h @ W2_r     (mean/matmul commuted)
// CSR gather aggregation + legacy mma.sync.m16n8k16 bf16 GEMMs with 2-term
// bf16 split (h+l, 3 products, fp32 accumulate).
// R12: all GEMM operands stored PRE-SPLIT as packed u32 (lo16=h, hi16=l):
// weights (g_w), agg1 mean (g_a1), hidden h (g_h). Fills unpack with 2 ALU
// ops/pair instead of cvt chains. Same arithmetic as R11.
// ---------------------------------------------------------------------------

#define NN 100000
#define EMAX 3200000
#define NB_SCAN 98            // ceil(NN/1024)

// float scratch: TR2 = [t2|r2] (N x 128)
__device__ float g_f[(size_t)NN * 128];
// packed bf16-split operands (lo16 = hi part, hi16 = lo part of the split)
__device__ unsigned g_a1[(size_t)NN * 128];   // mean_agg(x), packed
__device__ unsigned g_h [(size_t)NN * 128];   // hidden h, packed
__device__ unsigned g_w [3 * 16384];          // W1l | W1r | [W2l|W2r], packed

// int scratch  (CNT and TMP contiguous: one zeroing pass covers both)
constexpr size_t ROWPTR = 0;                             // NN+1
constexpr size_t CNT    = 100004;                        // NN
constexpr size_t TMP    = CNT + NN;                      // NN (contiguous)
constexpr size_t BSUM   = 300012;                        // 128
constexpr size_t SORTED = 300160;                        // EMAX
__device__ int g_i[SORTED + EMAX];
__device__ int g_idx64;

// ---- bf16 split + legacy mma helpers --------------------------------------
__device__ __forceinline__ void bsplit(float x, unsigned short& h, unsigned short& l) {
    __nv_bfloat16 hb = __float2bfloat16(x);
    __nv_bfloat16 lb = __float2bfloat16(x - __bfloat162float(hb));
    h = __bfloat16_as_ushort(hb);
    l = __bfloat16_as_ushort(lb);
}
__device__ __forceinline__ unsigned bpack(float x) {
    unsigned short h, l;
    bsplit(x, h, l);
    return (unsigned)h | ((unsigned)l << 16);
}
__device__ __forceinline__ void mma16(float* d, const unsigned* a, const unsigned* b) {
    asm volatile(
        "mma.sync.aligned.m16n8k16.row.col.f32.bf16.bf16.f32 "
        "{%0,%1,%2,%3}, {%4,%5,%6,%7}, {%8,%9}, {%0,%1,%2,%3};"
        : "+f"(d[0]), "+f"(d[1]), "+f"(d[2]), "+f"(d[3])
        : "r"(a[0]), "r"(a[1]), "r"(a[2]), "r"(a[3]), "r"(b[0]), "r"(b[1]));
}

// ---------------------------------------------------------------------------
// int64 vs int32 edge_index detection (values < 2^17 => odd words all zero)
// ---------------------------------------------------------------------------
__global__ void detect_kernel(const void* ei) {
    const int* w = (const int*)ei;
    int lane = threadIdx.x;
    int nz = 0;
    for (int i = lane * 2 + 1; i < 512; i += 64) nz |= (w[i] != 0);
    unsigned m = __ballot_sync(0xffffffffu, nz);
    if (lane == 0) g_idx64 = (m == 0) ? 1 : 0;
}

__global__ void zero_int_kernel() {
    int i = blockIdx.x * blockDim.x + threadIdx.x;
    if (i < 2 * NN) g_i[CNT + i] = 0;
}

// Pre-split all weights into packed bf16-pair format.
__global__ void split_w_kernel(const float* __restrict__ W1l,
                               const float* __restrict__ W1r,
                               const float* __restrict__ W2l,
                               const float* __restrict__ W2r) {
    int i = blockIdx.x * blockDim.x + threadIdx.x;
    if (i >= 3 * 16384) return;
    float v;
    if (i < 16384) v = W1l[i];
    else if (i < 32768) v = W1r[i - 16384];
    else {
        int j = i - 32768, k = j >> 7, n = j & 127;
        v = (n < 64) ? W2l[k * 64 + n] : W2r[k * 64 + (n - 64)];
    }
    g_w[i] = bpack(v);
}

__device__ __forceinline__ void load_edge(const void* ei, int e, int E, int& src, int& dst) {
    if (g_idx64) {
        const long long* p = (const long long*)ei;
        src = (int)p[e]; dst = (int)p[(size_t)E + e];
    } else {
        const int* p = (const int*)ei;
        src = p[e]; dst = p[(size_t)E + e];
    }
}

__global__ void hist_kernel(const void* __restrict__ ei, int E) {
    int e = blockIdx.x * blockDim.x + threadIdx.x;
    if (e >= E) return;
    int dst;
    if (g_idx64) dst = (int)((const long long*)ei)[(size_t)E + e];
    else         dst = ((const int*)ei)[(size_t)E + e];
    atomicAdd(&g_i[CNT + dst], 1);
}

__global__ void scan_a_kernel() {
    __shared__ int s[1024];
    int t = threadIdx.x;
    int i = blockIdx.x * 1024 + t;
    int v = (i < NN) ? g_i[CNT + i] : 0;
    s[t] = v;
    __syncthreads();
#pragma unroll
    for (int off = 1; off < 1024; off <<= 1) {
        int u = (t >= off) ? s[t - off] : 0;
        __syncthreads();
        s[t] += u;
        __syncthreads();
    }
    if (i < NN) g_i[ROWPTR + i + 1] = s[t];
    if (t == 1023) g_i[BSUM + blockIdx.x] = s[1023];
}

__global__ void scan_b_kernel() {
    __shared__ int s[128];
    int t = threadIdx.x;
    int v = (t < NB_SCAN) ? g_i[BSUM + t] : 0;
    s[t] = v;
    __syncthreads();
#pragma unroll
    for (int off = 1; off < 128; off <<= 1) {
        int u = (t >= off) ? s[t - off] : 0;
        __syncthreads();
        s[t] += u;
        __syncthreads();
    }
    if (t < NB_SCAN) g_i[BSUM + t] = s[t] - v;   // exclusive
}

__global__ void scan_c_kernel() {
    int i = blockIdx.x * blockDim.x + threadIdx.x;
    if (i < NN) g_i[ROWPTR + i + 1] += g_i[BSUM + (i >> 10)];
    if (i == 0) g_i[ROWPTR] = 0;
}

__global__ void scatter_kernel(const void* __restrict__ ei, int E) {
    int e = blockIdx.x * blockDim.x + threadIdx.x;
    if (e >= E) return;
    int src, dst;
    load_edge(ei, e, E, src, dst);
    int pos = g_i[ROWPTR + dst] + atomicAdd(&g_i[TMP + dst], 1);
    g_i[SORTED + pos] = src;
}

// ---------------------------------------------------------------------------
// Layer-1 aggregation: one warp per dst node, register accumulation,
// writes the MEAN packed as bf16 split (same numbers as splitting later).
// ---------------------------------------------------------------------------
__global__ __launch_bounds__(256) void agg1_kernel(const float* __restrict__ x) {
    int node = (int)(((size_t)blockIdx.x * blockDim.x + threadIdx.x) >> 5);
    if (node >= NN) return;
    int lane = threadIdx.x & 31;
    int beg = g_i[ROWPTR + node];
    int end = g_i[ROWPTR + node + 1];
    const int* srt = g_i + SORTED;
    float4 acc = make_float4(0.f, 0.f, 0.f, 0.f);
    int e = beg;
    for (; e + 4 <= end; e += 4) {
        int s0 = srt[e], s1 = srt[e + 1], s2 = srt[e + 2], s3 = srt[e + 3];
        float4 v0 = ((const float4*)(x + (size_t)s0 * 128))[lane];
        float4 v1 = ((const float4*)(x + (size_t)s1 * 128))[lane];
        float4 v2 = ((const float4*)(x + (size_t)s2 * 128))[lane];
        float4 v3 = ((const float4*)(x + (size_t)s3 * 128))[lane];
        acc.x += (v0.x + v1.x) + (v2.x + v3.x);
        acc.y += (v0.y + v1.y) + (v2.y + v3.y);
        acc.z += (v0.z + v1.z) + (v2.z + v3.z);
        acc.w += (v0.w + v1.w) + (v2.w + v3.w);
    }
    for (; e < end; e++) {
        float4 v = ((const float4*)(x + (size_t)srt[e] * 128))[lane];
        acc.x += v.x; acc.y += v.y; acc.z += v.z; acc.w += v.w;
    }
    float sc = 1.0f / fmaxf((float)(end - beg), 1.0f);
    uint4 pw;
    pw.x = bpack(acc.x * sc); pw.y = bpack(acc.y * sc);
    pw.z = bpack(acc.z * sc); pw.w = bpack(acc.w * sc);
    ((uint4*)(g_a1 + (size_t)node * 128))[lane] = pw;
}

// ---------------------------------------------------------------------------
// Shared GEMM tile machinery (legacy bf16 m16n8k16).
// A tile: 128 rows x 16 k -> Ah/Al packed bf16 pairs, word stride 12.
// B tile: 16 k x 128 n -> Bh/Bl as [n][k] ushort, stride 24 (=12 words).
// ---------------------------------------------------------------------------
struct GemmSmem {
    unsigned Ah[128][12], Al[128][12];
    unsigned short Bh[128][24], Bl[128][24];
};

// A-fill from packed u32 array: 2 ALU ops per bf16 pair, no converts.
__device__ __forceinline__ void fill_a_packed(GemmSmem& s, const unsigned* A,
                                              int row0, int kt, int t) {
#pragma unroll
    for (int l = 0; l < 2; l++) {
        int i = t + l * 256;
        int m = i >> 2, q = i & 3;
        uint4 w = make_uint4(0u, 0u, 0u, 0u);
        int gr = row0 + m;
        if (gr < NN) w = *(const uint4*)(A + (size_t)gr * 128 + kt + q * 4);
        s.Ah[m][2 * q + 0] = (w.x & 0xffffu) | (w.y << 16);
        s.Ah[m][2 * q + 1] = (w.z & 0xffffu) | (w.w << 16);
        s.Al[m][2 * q + 0] = (w.x >> 16) | (w.y & 0xffff0000u);
        s.Al[m][2 * q + 1] = (w.z >> 16) | (w.w & 0xffff0000u);
    }
}

// A-fill from fp32 (x operand): bsplit in the fill.
__device__ __forceinline__ void fill_a_f32(GemmSmem& s, const float* A,
                                           int row0, int kt, int t) {
#pragma unroll
    for (int l = 0; l < 2; l++) {
        int i = t + l * 256;
        int m = i >> 2, q = i & 3;
        float4 v = make_float4(0.f, 0.f, 0.f, 0.f);
        int gr = row0 + m;
        if (gr < NN) v = *(const float4*)(A + (size_t)gr * 128 + kt + q * 4);
        unsigned short h0, l0, h1, l1, h2, l2, h3, l3;
        bsplit(v.x, h0, l0); bsplit(v.y, h1, l1);
        bsplit(v.z, h2, l2); bsplit(v.w, h3, l3);
        s.Ah[m][2 * q + 0] = (unsigned)h0 | ((unsigned)h1 << 16);
        s.Ah[m][2 * q + 1] = (unsigned)h2 | ((unsigned)h3 << 16);
        s.Al[m][2 * q + 0] = (unsigned)l0 | ((unsigned)l1 << 16);
        s.Al[m][2 * q + 1] = (unsigned)l2 | ((unsigned)l3 << 16);
    }
}

// B-fill from packed weights: 1 load + 2 ALU ops per element.
__device__ __forceinline__ void fill_b_packed(GemmSmem& s, const unsigned* W,
                                              int kt, int t) {
#pragma unroll
    for (int l = 0; l < 8; l++) {
        int i = t + l * 256;
        int k = i >> 7, n = i & 127;
        unsigned w = W[(kt + k) * 128 + n];
        s.Bh[n][k] = (unsigned short)(w & 0xffffu);
        s.Bl[n][k] = (unsigned short)(w >> 16);
    }
}

// One K-16 step of the per-warp 32x64 tile: 2 mt x 8 nt x 3 products.
__device__ __forceinline__ void mma_step(GemmSmem& s, float acc[2][8][4],
                                         int warp_m, int warp_n, int g, int tg) {
    unsigned ah[2][4], al[2][4];
#pragma unroll
    for (int mt = 0; mt < 2; mt++) {
        int r = warp_m + mt * 16;
        ah[mt][0] = s.Ah[r + g][tg];      al[mt][0] = s.Al[r + g][tg];
        ah[mt][1] = s.Ah[r + g + 8][tg];  al[mt][1] = s.Al[r + g + 8][tg];
        ah[mt][2] = s.Ah[r + g][tg + 4];  al[mt][2] = s.Al[r + g][tg + 4];
        ah[mt][3] = s.Ah[r + g + 8][tg + 4]; al[mt][3] = s.Al[r + g + 8][tg + 4];
    }
#pragma unroll
    for (int nt = 0; nt < 8; nt++) {
        int n = warp_n + nt * 8 + g;
        unsigned bh[2], bl[2];
        bh[0] = ((const unsigned*)&s.Bh[n][0])[tg];
        bh[1] = ((const unsigned*)&s.Bh[n][0])[tg + 4];
        bl[0] = ((const unsigned*)&s.Bl[n][0])[tg];
        bl[1] = ((const unsigned*)&s.Bl[n][0])[tg + 4];
#pragma unroll
        for (int mt = 0; mt < 2; mt++) {
            mma16(acc[mt][nt], al[mt], bh);
            mma16(acc[mt][nt], ah[mt], bl);
            mma16(acc[mt][nt], ah[mt], bh);
        }
    }
}

// ---------------------------------------------------------------------------
// GEMM 1: h = relu( agg1 @ W1_l + x @ W1_r + b1 ); h written packed to g_h.
// ---------------------------------------------------------------------------
__global__ __launch_bounds__(256) void gemm1_kernel(
    const float* __restrict__ x, const float* __restrict__ b1) {
    __shared__ GemmSmem s;
    int t = threadIdx.x, lane = t & 31, wid = t >> 5;
    int row0 = blockIdx.x * 128;
    int warp_m = (wid & 3) * 32, warp_n = (wid >> 2) * 64;
    int g = lane >> 2, tg = lane & 3;

    float acc[2][8][4];
#pragma unroll
    for (int mt = 0; mt < 2; mt++)
#pragma unroll
        for (int nt = 0; nt < 8; nt++)
#pragma unroll
            for (int c = 0; c < 4; c++) acc[mt][nt][c] = 0.f;

    for (int pair = 0; pair < 2; pair++) {
        const unsigned* W = g_w + pair * 16384;
        for (int kt = 0; kt < 128; kt += 16) {
            if (pair == 0) fill_a_packed(s, g_a1, row0, kt, t);
            else           fill_a_f32(s, x, row0, kt, t);
            fill_b_packed(s, W, kt, t);
            __syncthreads();
            mma_step(s, acc, warp_m, warp_n, g, tg);
            __syncthreads();
        }
    }

#pragma unroll
    for (int mt = 0; mt < 2; mt++) {
#pragma unroll
        for (int nt = 0; nt < 8; nt++) {
            int col = warp_n + nt * 8 + tg * 2;
            float bx = b1[col], by = b1[col + 1];
            int rlo = row0 + warp_m + mt * 16 + g;
            if (rlo < NN) {
                uint2 pw;
                pw.x = bpack(fmaxf(acc[mt][nt][0] + bx, 0.f));
                pw.y = bpack(fmaxf(acc[mt][nt][1] + by, 0.f));
                *(uint2*)(g_h + (size_t)rlo * 128 + col) = pw;
            }
            int rhi = rlo + 8;
            if (rhi < NN) {
                uint2 pw;
                pw.x = bpack(fmaxf(acc[mt][nt][2] + bx, 0.f));
                pw.y = bpack(fmaxf(acc[mt][nt][3] + by, 0.f));
                *(uint2*)(g_h + (size_t)rhi * 128 + col) = pw;
            }
        }
    }
}

// ---------------------------------------------------------------------------
// GEMM 2: TR2 = h @ [W2_l | W2_r]   (M = NN, N = 128, K = 128)
// ---------------------------------------------------------------------------
__global__ __launch_bounds__(256) void gemm2_kernel() {
    __shared__ GemmSmem s;
    int t = threadIdx.x, lane = t & 31, wid = t >> 5;
    int row0 = blockIdx.x * 128;
    int warp_m = (wid & 3) * 32, warp_n = (wid >> 2) * 64;
    int g = lane >> 2, tg = lane & 3;

    float acc[2][8][4];
#pragma unroll
    for (int mt = 0; mt < 2; mt++)
#pragma unroll
        for (int nt = 0; nt < 8; nt++)
#pragma unroll
            for (int c = 0; c < 4; c++) acc[mt][nt][c] = 0.f;

    const unsigned* W = g_w + 2 * 16384;
    for (int kt = 0; kt < 128; kt += 16) {
        fill_a_packed(s, g_h, row0, kt, t);
        fill_b_packed(s, W, kt, t);
        __syncthreads();
        mma_step(s, acc, warp_m, warp_n, g, tg);
        __syncthreads();
    }

    float* tr2 = g_f;
#pragma unroll
    for (int mt = 0; mt < 2; mt++) {
#pragma unroll
        for (int nt = 0; nt < 8; nt++) {
            int col = warp_n + nt * 8 + tg * 2;
            int rlo = row0 + warp_m + mt * 16 + g;
            if (rlo < NN) {
                *(float2*)(tr2 + (size_t)rlo * 128 + col) =
                    make_float2(acc[mt][nt][0], acc[mt][nt][1]);
            }
            int rhi = rlo + 8;
            if (rhi < NN) {
                *(float2*)(tr2 + (size_t)rhi * 128 + col) =
                    make_float2(acc[mt][nt][2], acc[mt][nt][3]);
            }
        }
    }
}

// ---------------------------------------------------------------------------
// Layer-2 aggregation fused with epilogue:
//   out[i] = mean_{j in N(i)} t2[j] + b2 + r2[i]
// ---------------------------------------------------------------------------
__global__ __launch_bounds__(256) void agg2_kernel(const float* __restrict__ b2,
                                                   float* __restrict__ out) {
    int node = (int)(((size_t)blockIdx.x * blockDim.x + threadIdx.x) >> 5);
    if (node >= NN) return;
    int lane = threadIdx.x & 31;
    int beg = g_i[ROWPTR + node];
    int end = g_i[ROWPTR + node + 1];
    const int* srt = g_i + SORTED;
    const float* t2 = g_f;
    float2 acc = make_float2(0.f, 0.f);
    int e = beg;
    for (; e + 4 <= end; e += 4) {
        int s0 = srt[e], s1 = srt[e + 1], s2 = srt[e + 2], s3 = srt[e + 3];
        float2 v0 = ((const float2*)(t2 + (size_t)s0 * 128))[lane];
        float2 v1 = ((const float2*)(t2 + (size_t)s1 * 128))[lane];
        float2 v2 = ((const float2*)(t2 + (size_t)s2 * 128))[lane];
        float2 v3 = ((const float2*)(t2 + (size_t)s3 * 128))[lane];
        acc.x += (v0.x + v1.x) + (v2.x + v3.x);
        acc.y += (v0.y + v1.y) + (v2.y + v3.y);
    }
    for (; e < end; e++) {
        float2 v = ((const float2*)(t2 + (size_t)srt[e] * 128))[lane];
        acc.x += v.x; acc.y += v.y;
    }
    float sc = 1.0f / fmaxf((float)(end - beg), 1.0f);
    float2 r = ((const float2*)(t2 + (size_t)node * 128 + 64))[lane];
    float2 bb = ((const float2*)b2)[lane];
    float2 o;
    o.x = acc.x * sc + bb.x + r.x;
    o.y = acc.y * sc + bb.y + r.y;
    ((float2*)(out + (size_t)node * 64))[lane] = o;
}

extern "C" void kernel_launch(void* const* d_in, const int* in_sizes, int n_in,
                              void* d_out, int out_size) {
    const float* x   = (const float*)d_in[0];
    const float* W1l = (const float*)d_in[1];
    const float* b1  = (const float*)d_in[2];
    const float* W1r = (const float*)d_in[3];
    const float* W2l = (const float*)d_in[4];
    const float* b2  = (const float*)d_in[5];
    const float* W2r = (const float*)d_in[6];
    const void*  ei  = d_in[7];
    int E = in_sizes[7] / 2;
    if (E > EMAX) E = EMAX;
    float* out = (float*)d_out;

    detect_kernel<<<1, 32>>>(ei);
    zero_int_kernel<<<(2 * NN + 255) / 256, 256>>>();
    split_w_kernel<<<(3 * 16384 + 255) / 256, 256>>>(W1l, W1r, W2l, W2r);
    hist_kernel<<<(E + 255) / 256, 256>>>(ei, E);
    scan_a_kernel<<<NB_SCAN, 1024>>>();
    scan_b_kernel<<<1, 128>>>();
    scan_c_kernel<<<(NN + 255) / 256, 256>>>();
    scatter_kernel<<<(E + 255) / 256, 256>>>(ei, E);

    agg1_kernel<<<(NN * 32 + 255) / 256, 256>>>(x);
    gemm1_kernel<<<(NN + 127) / 128, 256>>>(x, b1);
    gemm2_kernel<<<(NN + 127) / 128, 256>>>();
    agg2_kernel<<<(NN * 32 + 255) / 256, 256>>>(b2, out);
}

// round 17
// speedup vs baseline: 1.7477x; 1.1652x over previous
#include <cuda_runtime.h>
#include <cuda_bf16.h>
#include <cstdint>

// ---------------------------------------------------------------------------
// GraphSAGE 2-layer, N=100000 nodes, E edges, d: 128 -> 128 -> 64, fp32.
//   h   = relu( mean_agg(x) @ W1_l + b1 + x @ W1_r )
//   out = mean_agg(h @ W2_l) + b2 + h @ W2_r     (mean/matmul commuted)
// CSR gather aggregation + mma.sync.m16n8k16 bf16 GEMMs (2-term bf16 split).
// R16: pipelined GEMMs with STATIC 48KB smem (no cudaFuncSetAttribute, no
// dynamic smem — suspected cause of the R13 container kills). cp.async
// 2-stage double buffer, K-tile 16, stride-24 rows (conflict-free LDS.64),
// prmt fragment extraction. Same arithmetic as R12. Replay idempotent.
// ---------------------------------------------------------------------------

#define NN 100000
#define EMAX 3200000
#define NB_SCAN 98            // ceil(NN/1024)

// float scratch: TR2 = [t2|r2] (N x 128)
__device__ float g_f[(size_t)NN * 128];
// packed bf16-split operands (lo16 = hi part, hi16 = lo part of split)
__device__ unsigned g_a1[(size_t)NN * 128];   // mean_agg(x), packed
__device__ unsigned g_x [(size_t)NN * 128];   // x, packed
__device__ unsigned g_h [(size_t)NN * 128];   // hidden h, packed
__device__ unsigned g_w [3 * 16384];          // transposed [n][k]: W1l|W1r|[W2l|W2r]

// int scratch  (CNT and TMP contiguous: one zeroing pass covers both)
constexpr size_t ROWPTR = 0;                             // NN+1
constexpr size_t CNT    = 100004;                        // NN
constexpr size_t TMP    = CNT + NN;                      // NN (contiguous)
constexpr size_t BSUM   = 300012;                        // 128
constexpr size_t SORTED = 300160;                        // EMAX
__device__ int g_i[SORTED + EMAX];
__device__ int g_idx64;

// ---- helpers ---------------------------------------------------------------
__device__ __forceinline__ void bsplit(float x, unsigned short& h, unsigned short& l) {
    __nv_bfloat16 hb = __float2bfloat16(x);
    __nv_bfloat16 lb = __float2bfloat16(x - __bfloat162float(hb));
    h = __bfloat16_as_ushort(hb);
    l = __bfloat16_as_ushort(lb);
}
__device__ __forceinline__ unsigned bpack(float x) {
    unsigned short h, l;
    bsplit(x, h, l);
    return (unsigned)h | ((unsigned)l << 16);
}
__device__ __forceinline__ void mma16(float* d, const unsigned* a, const unsigned* b) {
    asm volatile(
        "mma.sync.aligned.m16n8k16.row.col.f32.bf16.bf16.f32 "
        "{%0,%1,%2,%3}, {%4,%5,%6,%7}, {%8,%9}, {%0,%1,%2,%3};"
        : "+f"(d[0]), "+f"(d[1]), "+f"(d[2]), "+f"(d[3])
        : "r"(a[0]), "r"(a[1]), "r"(a[2]), "r"(a[3]), "r"(b[0]), "r"(b[1]));
}
__device__ __forceinline__ unsigned prmtw(unsigned a, unsigned b, unsigned s) {
    unsigned r;
    asm("prmt.b32 %0, %1, %2, %3;" : "=r"(r) : "r"(a), "r"(b), "r"(s));
    return r;
}
__device__ __forceinline__ uint32_t smem_u32(const void* p) {
    uint32_t a;
    asm("{ .reg .u64 t; cvta.to.shared.u64 t, %1; cvt.u32.u64 %0, t; }"
        : "=r"(a) : "l"(p));
    return a;
}
__device__ __forceinline__ void cp16(uint32_t dst, const void* src, int szbytes) {
    asm volatile("cp.async.cg.shared.global [%0], [%1], 16, %2;"
                 :: "r"(dst), "l"(src), "r"(szbytes));
}
#define CP_COMMIT() asm volatile("cp.async.commit_group;" ::: "memory")
#define CP_WAIT1()  asm volatile("cp.async.wait_group 1;"  ::: "memory")

// smem tile geometry: 128 rows x 16 packed words, row stride 24 words (96 B)
constexpr int TWW     = 128 * 24;        // 3072 words per tile
constexpr int STAGE_W = 2 * TWW;         // A + B per stage = 6144 words
// total static smem: 2 stages = 12288 words = 49152 B (fits 48KB static cap)

// ---------------------------------------------------------------------------
// int64 vs int32 edge_index detection (values < 2^17 => odd words all zero)
// ---------------------------------------------------------------------------
__global__ void detect_kernel(const void* ei) {
    const int* w = (const int*)ei;
    int lane = threadIdx.x;
    int nz = 0;
    for (int i = lane * 2 + 1; i < 512; i += 64) nz |= (w[i] != 0);
    unsigned m = __ballot_sync(0xffffffffu, nz);
    if (lane == 0) g_idx64 = (m == 0) ? 1 : 0;
}

__global__ void zero_int_kernel() {
    int i = blockIdx.x * blockDim.x + threadIdx.x;
    if (i < 2 * NN) g_i[CNT + i] = 0;
}

// Pre-split weights, TRANSPOSED to [n][k] packed.
__global__ void split_w_kernel(const float* __restrict__ W1l,
                               const float* __restrict__ W1r,
                               const float* __restrict__ W2l,
                               const float* __restrict__ W2r) {
    int i = blockIdx.x * blockDim.x + threadIdx.x;
    if (i >= 3 * 16384) return;
    int slot = i >> 14, j = i & 16383, n = j >> 7, k = j & 127;
    float v;
    if (slot == 0)      v = W1l[k * 128 + n];
    else if (slot == 1) v = W1r[k * 128 + n];
    else                v = (n < 64) ? W2l[k * 64 + n] : W2r[k * 64 + (n - 64)];
    g_w[i] = bpack(v);
}

// Pre-pack x.
__global__ void pack_x_kernel(const float* __restrict__ x) {
    size_t i = (size_t)blockIdx.x * blockDim.x + threadIdx.x;   // NN*32 float4s
    if (i < (size_t)NN * 32) {
        float4 v = ((const float4*)x)[i];
        uint4 p;
        p.x = bpack(v.x); p.y = bpack(v.y); p.z = bpack(v.z); p.w = bpack(v.w);
        ((uint4*)g_x)[i] = p;
    }
}

__device__ __forceinline__ void load_edge(const void* ei, int e, int E, int& src, int& dst) {
    if (g_idx64) {
        const long long* p = (const long long*)ei;
        src = (int)p[e]; dst = (int)p[(size_t)E + e];
    } else {
        const int* p = (const int*)ei;
        src = p[e]; dst = p[(size_t)E + e];
    }
}

__global__ void hist_kernel(const void* __restrict__ ei, int E) {
    int e = blockIdx.x * blockDim.x + threadIdx.x;
    if (e >= E) return;
    int dst;
    if (g_idx64) dst = (int)((const long long*)ei)[(size_t)E + e];
    else         dst = ((const int*)ei)[(size_t)E + e];
    atomicAdd(&g_i[CNT + dst], 1);
}

__global__ void scan_a_kernel() {
    __shared__ int s[1024];
    int t = threadIdx.x;
    int i = blockIdx.x * 1024 + t;
    int v = (i < NN) ? g_i[CNT + i] : 0;
    s[t] = v;
    __syncthreads();
#pragma unroll
    for (int off = 1; off < 1024; off <<= 1) {
        int u = (t >= off) ? s[t - off] : 0;
        __syncthreads();
        s[t] += u;
        __syncthreads();
    }
    if (i < NN) g_i[ROWPTR + i + 1] = s[t];
    if (t == 1023) g_i[BSUM + blockIdx.x] = s[1023];
}

__global__ void scan_b_kernel() {
    __shared__ int s[128];
    int t = threadIdx.x;
    int v = (t < NB_SCAN) ? g_i[BSUM + t] : 0;
    s[t] = v;
    __syncthreads();
#pragma unroll
    for (int off = 1; off < 128; off <<= 1) {
        int u = (t >= off) ? s[t - off] : 0;
        __syncthreads();
        s[t] += u;
        __syncthreads();
    }
    if (t < NB_SCAN) g_i[BSUM + t] = s[t] - v;   // exclusive
}

__global__ void scan_c_kernel() {
    int i = blockIdx.x * blockDim.x + threadIdx.x;
    if (i < NN) g_i[ROWPTR + i + 1] += g_i[BSUM + (i >> 10)];
    if (i == 0) g_i[ROWPTR] = 0;
}

__global__ void scatter_kernel(const void* __restrict__ ei, int E) {
    int e = blockIdx.x * blockDim.x + threadIdx.x;
    if (e >= E) return;
    int src, dst;
    load_edge(ei, e, E, src, dst);
    int pos = g_i[ROWPTR + dst] + atomicAdd(&g_i[TMP + dst], 1);
    g_i[SORTED + pos] = src;
}

// ---------------------------------------------------------------------------
// Layer-1 aggregation: one warp per dst node, fp32 accumulation, packed write.
// ---------------------------------------------------------------------------
__global__ __launch_bounds__(256) void agg1_kernel(const float* __restrict__ x) {
    int node = (int)(((size_t)blockIdx.x * blockDim.x + threadIdx.x) >> 5);
    if (node >= NN) return;
    int lane = threadIdx.x & 31;
    int beg = g_i[ROWPTR + node];
    int end = g_i[ROWPTR + node + 1];
    const int* srt = g_i + SORTED;
    float4 acc = make_float4(0.f, 0.f, 0.f, 0.f);
    int e = beg;
    for (; e + 4 <= end; e += 4) {
        int s0 = srt[e], s1 = srt[e + 1], s2 = srt[e + 2], s3 = srt[e + 3];
        float4 v0 = ((const float4*)(x + (size_t)s0 * 128))[lane];
        float4 v1 = ((const float4*)(x + (size_t)s1 * 128))[lane];
        float4 v2 = ((const float4*)(x + (size_t)s2 * 128))[lane];
        float4 v3 = ((const float4*)(x + (size_t)s3 * 128))[lane];
        acc.x += (v0.x + v1.x) + (v2.x + v3.x);
        acc.y += (v0.y + v1.y) + (v2.y + v3.y);
        acc.z += (v0.z + v1.z) + (v2.z + v3.z);
        acc.w += (v0.w + v1.w) + (v2.w + v3.w);
    }
    for (; e < end; e++) {
        float4 v = ((const float4*)(x + (size_t)srt[e] * 128))[lane];
        acc.x += v.x; acc.y += v.y; acc.z += v.z; acc.w += v.w;
    }
    float sc = 1.0f / fmaxf((float)(end - beg), 1.0f);
    uint4 pw;
    pw.x = bpack(acc.x * sc); pw.y = bpack(acc.y * sc);
    pw.z = bpack(acc.z * sc); pw.w = bpack(acc.w * sc);
    ((uint4*)(g_a1 + (size_t)node * 128))[lane] = pw;
}

// ---------------------------------------------------------------------------
// Pipelined GEMM machinery (K-tile 16, static smem)
// ---------------------------------------------------------------------------
// Fill stage s: A rows [row0,row0+128) x k [kt,kt+16), B rows n x same k.
__device__ __forceinline__ void fill_stage(uint32_t sbase, int s,
                                           const unsigned* A, const unsigned* B,
                                           int row0, int kt, int t) {
#pragma unroll
    for (int l = 0; l < 2; l++) {
        int c = t + l * 256;                 // 0..511
        int row = c >> 2, c16 = c & 3;       // 4 x 16B chunks per 16-word row
        uint32_t so = sbase + (uint32_t)s * (STAGE_W * 4) + row * 96 + c16 * 16;
        int gr = row0 + row;
        int grc = (gr < NN) ? gr : (NN - 1);
        cp16(so, A + (size_t)grc * 128 + kt + c16 * 4, (gr < NN) ? 16 : 0);
        cp16(so + (uint32_t)(TWW * 4), B + row * 128 + kt + c16 * 4, 16);
    }
}

// One K-16 tile of the per-warp 32x64 sub-GEMM (3 split products).
__device__ __forceinline__ void mma_tile(const unsigned* sA, const unsigned* sB,
                                         float acc[2][8][4],
                                         int warp_m, int warp_n, int g, int tg) {
    int w0 = 2 * tg;
    unsigned ah[2][4], al[2][4];
#pragma unroll
    for (int mt = 0; mt < 2; mt++) {
        int r = warp_m + mt * 16 + g;
        uint2 p0 = *(const uint2*)(sA + r * 24 + w0);
        uint2 p1 = *(const uint2*)(sA + (r + 8) * 24 + w0);
        uint2 p2 = *(const uint2*)(sA + r * 24 + w0 + 8);
        uint2 p3 = *(const uint2*)(sA + (r + 8) * 24 + w0 + 8);
        ah[mt][0] = prmtw(p0.x, p0.y, 0x5410u); al[mt][0] = prmtw(p0.x, p0.y, 0x7632u);
        ah[mt][1] = prmtw(p1.x, p1.y, 0x5410u); al[mt][1] = prmtw(p1.x, p1.y, 0x7632u);
        ah[mt][2] = prmtw(p2.x, p2.y, 0x5410u); al[mt][2] = prmtw(p2.x, p2.y, 0x7632u);
        ah[mt][3] = prmtw(p3.x, p3.y, 0x5410u); al[mt][3] = prmtw(p3.x, p3.y, 0x7632u);
    }
#pragma unroll
    for (int nt = 0; nt < 8; nt++) {
        int n = warp_n + nt * 8 + g;
        uint2 q0 = *(const uint2*)(sB + n * 24 + w0);
        uint2 q1 = *(const uint2*)(sB + n * 24 + w0 + 8);
        unsigned bh[2], bl[2];
        bh[0] = prmtw(q0.x, q0.y, 0x5410u); bl[0] = prmtw(q0.x, q0.y, 0x7632u);
        bh[1] = prmtw(q1.x, q1.y, 0x5410u); bl[1] = prmtw(q1.x, q1.y, 0x7632u);
#pragma unroll
        for (int mt = 0; mt < 2; mt++) {
            mma16(acc[mt][nt], al[mt], bh);
            mma16(acc[mt][nt], ah[mt], bl);
            mma16(acc[mt][nt], ah[mt], bh);
        }
    }
}

// ---------------------------------------------------------------------------
// GEMM 1: h = relu( agg1 @ W1_l + x @ W1_r + b1 ); h written packed to g_h.
// 16 tiles: tt<8 -> (g_a1, W1l), tt>=8 -> (g_x, W1r); kt = (tt&7)*16.
// ---------------------------------------------------------------------------
__global__ __launch_bounds__(256) void gemm1_kernel(const float* __restrict__ b1) {
    __shared__ unsigned sm[2 * STAGE_W];   // 49152 B static
    uint32_t sbase = smem_u32(sm);
    int t = threadIdx.x, lane = t & 31, wid = t >> 5;
    int row0 = blockIdx.x * 128;
    int warp_m = (wid & 3) * 32, warp_n = (wid >> 2) * 64;
    int g = lane >> 2, tg = lane & 3;

    float acc[2][8][4];
#pragma unroll
    for (int mt = 0; mt < 2; mt++)
#pragma unroll
        for (int nt = 0; nt < 8; nt++)
#pragma unroll
            for (int c = 0; c < 4; c++) acc[mt][nt][c] = 0.f;

    const int T = 16;
    fill_stage(sbase, 0, g_a1, g_w, row0, 0, t);  CP_COMMIT();
    fill_stage(sbase, 1, g_a1, g_w, row0, 16, t); CP_COMMIT();
    for (int tt = 0; tt < T; tt++) {
        CP_WAIT1();
        __syncthreads();
        const unsigned* sA = sm + (tt & 1) * STAGE_W;
        const unsigned* sB = sA + TWW;
        mma_tile(sA, sB, acc, warp_m, warp_n, g, tg);
        __syncthreads();
        int nx = tt + 2;
        if (nx < T) {
            const unsigned* A = (nx >> 3) ? g_x : g_a1;
            const unsigned* B = g_w + (nx >> 3) * 16384;
            fill_stage(sbase, nx & 1, A, B, row0, (nx & 7) * 16, t);
        }
        CP_COMMIT();
    }

#pragma unroll
    for (int mt = 0; mt < 2; mt++) {
#pragma unroll
        for (int nt = 0; nt < 8; nt++) {
            int col = warp_n + nt * 8 + tg * 2;
            float bx = b1[col], by = b1[col + 1];
            int rlo = row0 + warp_m + mt * 16 + g;
            if (rlo < NN) {
                uint2 pw;
                pw.x = bpack(fmaxf(acc[mt][nt][0] + bx, 0.f));
                pw.y = bpack(fmaxf(acc[mt][nt][1] + by, 0.f));
                *(uint2*)(g_h + (size_t)rlo * 128 + col) = pw;
            }
            int rhi = rlo + 8;
            if (rhi < NN) {
                uint2 pw;
                pw.x = bpack(fmaxf(acc[mt][nt][2] + bx, 0.f));
                pw.y = bpack(fmaxf(acc[mt][nt][3] + by, 0.f));
                *(uint2*)(g_h + (size_t)rhi * 128 + col) = pw;
            }
        }
    }
}

// ---------------------------------------------------------------------------
// GEMM 2: TR2 = h @ [W2_l | W2_r]   (M = NN, N = 128, K = 128); 8 tiles.
// ---------------------------------------------------------------------------
__global__ __launch_bounds__(256) void gemm2_kernel() {
    __shared__ unsigned sm[2 * STAGE_W];
    uint32_t sbase = smem_u32(sm);
    int t = threadIdx.x, lane = t & 31, wid = t >> 5;
    int row0 = blockIdx.x * 128;
    int warp_m = (wid & 3) * 32, warp_n = (wid >> 2) * 64;
    int g = lane >> 2, tg = lane & 3;

    float acc[2][8][4];
#pragma unroll
    for (int mt = 0; mt < 2; mt++)
#pragma unroll
        for (int nt = 0; nt < 8; nt++)
#pragma unroll
            for (int c = 0; c < 4; c++) acc[mt][nt][c] = 0.f;

    const unsigned* W = g_w + 2 * 16384;
    const int T = 8;
    fill_stage(sbase, 0, g_h, W, row0, 0, t);  CP_COMMIT();
    fill_stage(sbase, 1, g_h, W, row0, 16, t); CP_COMMIT();
    for (int tt = 0; tt < T; tt++) {
        CP_WAIT1();
        __syncthreads();
        const unsigned* sA = sm + (tt & 1) * STAGE_W;
        const unsigned* sB = sA + TWW;
        mma_tile(sA, sB, acc, warp_m, warp_n, g, tg);
        __syncthreads();
        int nx = tt + 2;
        if (nx < T) fill_stage(sbase, nx & 1, g_h, W, row0, nx * 16, t);
        CP_COMMIT();
    }

    float* tr2 = g_f;
#pragma unroll
    for (int mt = 0; mt < 2; mt++) {
#pragma unroll
        for (int nt = 0; nt < 8; nt++) {
            int col = warp_n + nt * 8 + tg * 2;
            int rlo = row0 + warp_m + mt * 16 + g;
            if (rlo < NN) {
                *(float2*)(tr2 + (size_t)rlo * 128 + col) =
                    make_float2(acc[mt][nt][0], acc[mt][nt][1]);
            }
            int rhi = rlo + 8;
            if (rhi < NN) {
                *(float2*)(tr2 + (size_t)rhi * 128 + col) =
                    make_float2(acc[mt][nt][2], acc[mt][nt][3]);
            }
        }
    }
}

// ---------------------------------------------------------------------------
// Layer-2 aggregation fused with epilogue:
//   out[i] = mean_{j in N(i)} t2[j] + b2 + r2[i]
// ---------------------------------------------------------------------------
__global__ __launch_bounds__(256) void agg2_kernel(const float* __restrict__ b2,
                                                   float* __restrict__ out) {
    int node = (int)(((size_t)blockIdx.x * blockDim.x + threadIdx.x) >> 5);
    if (node >= NN) return;
    int lane = threadIdx.x & 31;
    int beg = g_i[ROWPTR + node];
    int end = g_i[ROWPTR + node + 1];
    const int* srt = g_i + SORTED;
    const float* t2 = g_f;
    float2 acc = make_float2(0.f, 0.f);
    int e = beg;
    for (; e + 4 <= end; e += 4) {
        int s0 = srt[e], s1 = srt[e + 1], s2 = srt[e + 2], s3 = srt[e + 3];
        float2 v0 = ((const float2*)(t2 + (size_t)s0 * 128))[lane];
        float2 v1 = ((const float2*)(t2 + (size_t)s1 * 128))[lane];
        float2 v2 = ((const float2*)(t2 + (size_t)s2 * 128))[lane];
        float2 v3 = ((const float2*)(t2 + (size_t)s3 * 128))[lane];
        acc.x += (v0.x + v1.x) + (v2.x + v3.x);
        acc.y += (v0.y + v1.y) + (v2.y + v3.y);
    }
    for (; e < end; e++) {
        float2 v = ((const float2*)(t2 + (size_t)srt[e] * 128))[lane];
        acc.x += v.x; acc.y += v.y;
    }
    float sc = 1.0f / fmaxf((float)(end - beg), 1.0f);
    float2 r = ((const float2*)(t2 + (size_t)node * 128 + 64))[lane];
    float2 bb = ((const float2*)b2)[lane];
    float2 o;
    o.x = acc.x * sc + bb.x + r.x;
    o.y = acc.y * sc + bb.y + r.y;
    ((float2*)(out + (size_t)node * 64))[lane] = o;
}

extern "C" void kernel_launch(void* const* d_in, const int* in_sizes, int n_in,
                              void* d_out, int out_size) {
    const float* x   = (const float*)d_in[0];
    const float* W1l = (const float*)d_in[1];
    const float* b1  = (const float*)d_in[2];
    const float* W1r = (const float*)d_in[3];
    const float* W2l = (const float*)d_in[4];
    const float* b2  = (const float*)d_in[5];
    const float* W2r = (const float*)d_in[6];
    const void*  ei  = d_in[7];
    int E = in_sizes[7] / 2;
    if (E > EMAX) E = EMAX;
    float* out = (float*)d_out;

    detect_kernel<<<1, 32>>>(ei);
    zero_int_kernel<<<(2 * NN + 255) / 256, 256>>>();
    split_w_kernel<<<(3 * 16384 + 255) / 256, 256>>>(W1l, W1r, W2l, W2r);
    pack_x_kernel<<<(NN * 32 + 255) / 256, 256>>>(x);
    hist_kernel<<<(E + 255) / 256, 256>>>(ei, E);
    scan_a_kernel<<<NB_SCAN, 1024>>>();
    scan_b_kernel<<<1, 128>>>();
    scan_c_kernel<<<(NN + 255) / 256, 256>>>();
    scatter_kernel<<<(E + 255) / 256, 256>>>(ei, E);

    agg1_kernel<<<(NN * 32 + 255) / 256, 256>>>(x);
    gemm1_kernel<<<(NN + 127) / 128, 256>>>(b1);
    gemm2_kernel<<<(NN + 127) / 128, 256>>>();
    agg2_kernel<<<(NN * 32 + 255) / 256, 256>>>(b2, out);
}